// round 3
// baseline (speedup 1.0000x reference)
#include <cuda_runtime.h>

// Problem dims (fixed by setup_inputs): B=1, C=32, H=128, W=256, D=48
// out: [1, 2C=64, D=48, H=128, W=256] f32
#define HH 128
#define WW 256
#define CC 32
#define DD 48

constexpr int HW    = HH * WW;        // 32768
constexpr long DHW  = (long)DD * HW;  // 1572864
constexpr int SM_ROW = CC * WW;       // 8192 floats per cached y-row (all 32 channels)

__global__ __launch_bounds__(256, 1)
void cost_volume_kernel(const float* __restrict__ x,
                        const float* __restrict__ y,
                        const float* __restrict__ disp,
                        float* __restrict__ out)
{
    extern __shared__ float smY[];   // [2 rows][32 c][256 x] = 64 KB

    const int h      = blockIdx.y;   // 0..127
    const int dchunk = blockIdx.x;   // 0..11  (4 d per block)
    const int tid    = threadIdx.x;  // 256 threads

    // iy depends only on h (align_corners=False unnormalize of align_corners=True grid)
    // gy+1 = h / 63.5 ; iy = ((gy+1)*H - 1) * 0.5
    const float gy1 = (float)h / 63.5f;
    const float iy  = (gy1 * 128.0f - 1.0f) * 0.5f;
    const float y0f = floorf(iy);
    const float wy  = iy - y0f;
    const int   y0  = (int)y0f;

    // Cooperatively stage the two y rows into smem (zero-fill OOB rows -> handles
    // the row part of zeros padding for free).
    #pragma unroll
    for (int r = 0; r < 2; ++r) {
        const int  yr    = y0 + r;
        const bool valid = ((unsigned)yr < (unsigned)HH);
        for (int i = tid; i < CC * (WW / 4); i += 256) {
            const int c  = i >> 6;          // 0..31
            const int x4 = (i & 63) << 2;   // 0,4,...,252
            float4 v = make_float4(0.f, 0.f, 0.f, 0.f);
            if (valid)
                v = *(const float4*)(y + (c * HH + yr) * WW + x4);
            *(float4*)(smY + r * SM_ROW + c * WW + x4) = v;
        }
    }
    __syncthreads();

    // Thread mapping: tid>>6 = local d (0..3), tid&63 -> 4 consecutive w
    const int dloc = tid >> 6;
    const int d    = dchunk * 4 + dloc;
    const int w0   = (tid & 63) << 2;

    // Disparities for the 4 w positions (coalesced float4 load)
    const float4 dv = *(const float4*)(disp + (d * HH + h) * WW + w0);
    const float darr[4] = {dv.x, dv.y, dv.z, dv.w};

    int   xa[4], xb[4];
    float w00[4], w01[4], w10[4], w11[4];
    const float omwy = 1.0f - wy;

    #pragma unroll
    for (int j = 0; j < 4; ++j) {
        const float cur = (float)(w0 + j) - darr[j];
        // gx+1 = cur / 127.5 ; ix = ((gx+1)*W - 1) * 0.5
        const float t   = cur / 127.5f;
        const float ixv = (t * 256.0f - 1.0f) * 0.5f;
        const float x0f = floorf(ixv);
        const float wx  = ixv - x0f;
        const int   x0  = (int)x0f;
        const int   x1  = x0 + 1;
        const float m0  = ((unsigned)x0 < (unsigned)WW) ? 1.0f : 0.0f;
        const float m1  = ((unsigned)x1 < (unsigned)WW) ? 1.0f : 0.0f;
        xa[j] = min(max(x0, 0), WW - 1);
        xb[j] = min(max(x1, 0), WW - 1);
        const float omwx = 1.0f - wx;
        w00[j] = omwx * omwy * m0;   // (y0,x0)
        w01[j] = wx   * omwy * m1;   // (y0,x1)
        w10[j] = omwx * wy   * m0;   // (y1,x0)
        w11[j] = wx   * wy   * m1;   // (y1,x1)
    }

    // Output bases: left half = channels [0,32), warped half = channels [32,64)
    const float* xrow = x + h * WW + w0;
    float* outL = out + (long)d * HW + (long)h * WW + w0;                    // c=0 (left)
    float* outR = out + (long)CC * DHW + (long)d * HW + (long)h * WW + w0;   // c=32 (warped)

    #pragma unroll 4
    for (int c = 0; c < CC; ++c) {
        const float* r0 = smY + c * WW;        // row y0, channel c
        const float* r1 = r0 + SM_ROW;         // row y0+1, channel c

        float4 o;
        o.x = r0[xa[0]] * w00[0] + r0[xb[0]] * w01[0] + r1[xa[0]] * w10[0] + r1[xb[0]] * w11[0];
        o.y = r0[xa[1]] * w00[1] + r0[xb[1]] * w01[1] + r1[xa[1]] * w10[1] + r1[xb[1]] * w11[1];
        o.z = r0[xa[2]] * w00[2] + r0[xb[2]] * w01[2] + r1[xa[2]] * w10[2] + r1[xb[2]] * w11[2];
        o.w = r0[xa[3]] * w00[3] + r0[xb[3]] * w01[3] + r1[xa[3]] * w10[3] + r1[xb[3]] * w11[3];
        *(float4*)(outR + (long)c * DHW) = o;

        // Left half: broadcast x over d (x row is L1-hot across the block's 4 d's)
        const float4 xv = __ldg((const float4*)(xrow + c * HW));
        *(float4*)(outL + (long)c * DHW) = xv;
    }
}

extern "C" void kernel_launch(void* const* d_in, const int* in_sizes, int n_in,
                              void* d_out, int out_size)
{
    const float* x    = (const float*)d_in[0];
    const float* y    = (const float*)d_in[1];
    const float* disp = (const float*)d_in[2];
    float* out = (float*)d_out;

    const int smem_bytes = 2 * SM_ROW * (int)sizeof(float);  // 64 KB
    cudaFuncSetAttribute(cost_volume_kernel,
                         cudaFuncAttributeMaxDynamicSharedMemorySize, smem_bytes);

    dim3 grid(DD / 4, HH);   // (12, 128) = 1536 blocks
    cost_volume_kernel<<<grid, 256, smem_bytes>>>(x, y, disp, out);
}